// round 8
// baseline (speedup 1.0000x reference)
#include <cuda_runtime.h>
#include <cuda_fp16.h>
#include <cstdint>

// TEPRNN2 via warp MMA (HMMA), gate-split: 16 warps = (batch-half, gate-pair, unit-block).
// role0 = gates (i,g), role1 = gates (f,o); cross-warp 'a' exchange via SMEM.
// fp16 hi/lo split (3 MMAs for W_hh tiles, 2 for fc1/bias tile), fp32 accum.

#define S_LEN   256
#define THREADS 512
#define BPB     32
#define HST     88     // halfs per batch column (80 + 8 pad)
#define AST     68     // floats per a-exchange column (64 + 4 pad)

__device__ __forceinline__ float sigm_f(float x){
    x = fminf(fmaxf(x, -30.f), 30.f);
    float e = __expf(-x);
    return __fdividef(1.f, 1.f + e);
}
__device__ __forceinline__ float tanh_f(float x){
    x = fminf(fmaxf(x, -15.f), 15.f);
    float e = __expf(-2.f * x);
    return __fdividef(1.f - e, 1.f + e);
}
__device__ __forceinline__ uint32_t pk(float a, float b){
    __half2 t = __halves2half2(__float2half_rn(a), __float2half_rn(b));
    return *reinterpret_cast<uint32_t*>(&t);
}
__device__ __forceinline__ void mma16816(float* d, const uint32_t* a,
                                         uint32_t b0, uint32_t b1){
    asm volatile(
        "mma.sync.aligned.m16n8k16.row.col.f32.f16.f16.f32 "
        "{%0,%1,%2,%3}, {%4,%5,%6,%7}, {%8,%9}, {%0,%1,%2,%3};"
        : "+f"(d[0]), "+f"(d[1]), "+f"(d[2]), "+f"(d[3])
        : "r"(a[0]), "r"(a[1]), "r"(a[2]), "r"(a[3]), "r"(b0), "r"(b1));
}
__device__ __forceinline__ void barh(int id){
    asm volatile("bar.sync %0, 256;" :: "r"(id) : "memory");
}

__global__ __launch_bounds__(THREADS, 1)
void teprnn2_mma2(const float* __restrict__ x,
                  const float* __restrict__ W1,
                  const float* __restrict__ b1,
                  const float* __restrict__ W_ih,
                  const float* __restrict__ W_hh,
                  const float* __restrict__ b_ih,
                  const float* __restrict__ b_hh,
                  const float* __restrict__ W2,
                  const float* __restrict__ b2,
                  float* __restrict__ out)
{
    __shared__ __half hHI[2][2][16][HST];   // [np][buf][batch-col][k]
    __shared__ __half hLO[2][2][16][HST];
    __shared__ float  aEx[2][16][AST];      // [np][batch-col][unit]
    __shared__ float  hfin[32][65];

    const int tid  = threadIdx.x;
    const int wid  = tid >> 5;
    const int lane = tid & 31;
    const int ub   = wid & 3;          // unit block (16 units) -> also SMSP id
    const int role = (wid >> 2) & 1;   // 0 = gates (i,g), 1 = gates (f,o)
    const int np   = wid >> 3;         // batch half
    const int r0   = lane >> 2;
    const int k0   = (lane & 3) * 2;
    const int bbase = blockIdx.x * BPB;

    // ---- A fragments for this warp's 2 gates: gate = 2*gi + role ----
    uint32_t Ah[2][5][4], Al[2][4][4];
    #pragma unroll
    for (int gi = 0; gi < 2; ++gi) {
        const int g   = 2 * gi + role;
        const int gr0 = g * 64 + ub * 16 + r0;
        #pragma unroll
        for (int kt = 0; kt < 4; ++kt) {
            const int kb = kt * 16 + k0;
            float v[8];
            v[0] = W_hh[gr0 * 64 + kb];        v[1] = W_hh[gr0 * 64 + kb + 1];
            v[2] = W_hh[(gr0+8) * 64 + kb];    v[3] = W_hh[(gr0+8) * 64 + kb + 1];
            v[4] = W_hh[gr0 * 64 + kb + 8];    v[5] = W_hh[gr0 * 64 + kb + 9];
            v[6] = W_hh[(gr0+8) * 64 + kb + 8];v[7] = W_hh[(gr0+8) * 64 + kb + 9];
            float hi[8], lo[8];
            #pragma unroll
            for (int e = 0; e < 8; ++e) {
                hi[e] = __half2float(__float2half_rn(v[e]));
                lo[e] = v[e] - hi[e];
            }
            Ah[gi][kt][0] = pk(hi[0], hi[1]);  Al[gi][kt][0] = pk(lo[0], lo[1]);
            Ah[gi][kt][1] = pk(hi[2], hi[3]);  Al[gi][kt][1] = pk(lo[2], lo[3]);
            Ah[gi][kt][2] = pk(hi[4], hi[5]);  Al[gi][kt][2] = pk(lo[4], lo[5]);
            Ah[gi][kt][3] = pk(hi[6], hi[7]);  Al[gi][kt][3] = pk(lo[6], lo[7]);
        }
        {   // kt = 4: rows k=64..71 (W_ih + bias@68) in slots 0,1; k=72..79 zero
            const int ka = 64 + k0, kb2 = ka + 1;
            float va = (ka  < 68) ? W_ih[gr0*4 + (ka-64)]      : (ka  == 68 ? b_ih[gr0]   + b_hh[gr0]   : 0.f);
            float vb = (kb2 < 68) ? W_ih[gr0*4 + (kb2-64)]     : (kb2 == 68 ? b_ih[gr0]   + b_hh[gr0]   : 0.f);
            float vc = (ka  < 68) ? W_ih[(gr0+8)*4 + (ka-64)]  : (ka  == 68 ? b_ih[gr0+8] + b_hh[gr0+8] : 0.f);
            float vd = (kb2 < 68) ? W_ih[(gr0+8)*4 + (kb2-64)] : (kb2 == 68 ? b_ih[gr0+8] + b_hh[gr0+8] : 0.f);
            Ah[gi][4][0] = pk(__half2float(__float2half_rn(va)), __half2float(__float2half_rn(vb)));
            Ah[gi][4][1] = pk(__half2float(__float2half_rn(vc)), __half2float(__float2half_rn(vd)));
            Ah[gi][4][2] = 0u;
            Ah[gi][4][3] = 0u;
        }
    }

    // ---- fc1 duty (role0 warps: 128 threads per half) ----
    const int lt = ub * 32 + lane;     // 0..127 within role-half group
    const int lb = lt >> 3;
    const int fi = (lt >> 1) & 3;
    const int pr = lt & 1;
    const float w1r = __ldg(W1 + fi);
    const float b1r = __ldg(b1 + fi);
    const float* xrow = x + (size_t)(bbase + np * 16 + lb) * S_LEN;

    {   // zero both B arrays
        __half* p0 = &hHI[0][0][0][0];
        __half* p1 = &hLO[0][0][0][0];
        for (int i = tid; i < 2 * 2 * 16 * HST; i += THREADS) {
            p0[i] = __ushort_as_half(0); p1[i] = __ushort_as_half(0);
        }
    }
    __syncthreads();
    if (tid < 64) {  // const-1 row (k=68), both halves x both bufs
        int idx = tid >> 4;
        hHI[idx >> 1][idx & 1][tid & 15][68] = __float2half_rn(1.f);
    }
    if (role == 0) {  // fc1 for step 0 -> buf 0
        float v  = tanh_f(fmaf(__ldg(xrow + 0), w1r, b1r));
        float vh = __half2float(__float2half_rn(v));
        if (pr == 0) hHI[np][0][lb][64 + fi] = __float2half_rn(v);
        else         hLO[np][0][lb][64 + fi] = __float2half_rn(v - vh);
    }
    __syncthreads();

    float cst[2][4];
    #pragma unroll
    for (int nt = 0; nt < 2; ++nt)
        #pragma unroll
        for (int e = 0; e < 4; ++e) cst[nt][e] = 0.f;

    const int bar1 = np * 2 + 1;
    const int bar2 = np * 2 + 2;

    int buf = 0;
    for (int s = 0; s < S_LEN; ++s) {
        float xv = 0.f;
        if (role == 0 && s + 1 < S_LEN) xv = __ldg(xrow + s + 1);

        float d[2][2][4];
        #pragma unroll
        for (int gi = 0; gi < 2; ++gi)
            #pragma unroll
            for (int nt = 0; nt < 2; ++nt)
                #pragma unroll
                for (int e = 0; e < 4; ++e) d[gi][nt][e] = 0.f;

        const __half* bhp = &hHI[np][buf][0][0];
        const __half* blp = &hLO[np][buf][0][0];

        #pragma unroll
        for (int kt = 0; kt < 4; ++kt) {
            #pragma unroll
            for (int nt = 0; nt < 2; ++nt) {
                const int idx = (nt * 8 + r0) * HST + kt * 16 + k0;
                uint32_t bh0 = *(const uint32_t*)(bhp + idx);
                uint32_t bh1 = *(const uint32_t*)(bhp + idx + 8);
                uint32_t bl0 = *(const uint32_t*)(blp + idx);
                uint32_t bl1 = *(const uint32_t*)(blp + idx + 8);
                #pragma unroll
                for (int gi = 0; gi < 2; ++gi) {
                    mma16816(d[gi][nt], Ah[gi][kt], bh0, bh1);
                    mma16816(d[gi][nt], Al[gi][kt], bh0, bh1);
                    mma16816(d[gi][nt], Ah[gi][kt], bl0, bl1);
                }
            }
        }
        #pragma unroll
        for (int nt = 0; nt < 2; ++nt) {   // kt=4: fc1 + bias (hi A only)
            const int idx = (nt * 8 + r0) * HST + 64 + k0;
            uint32_t bh0 = *(const uint32_t*)(bhp + idx);
            uint32_t bl0 = *(const uint32_t*)(blp + idx);
            #pragma unroll
            for (int gi = 0; gi < 2; ++gi) {
                mma16816(d[gi][nt], Ah[gi][4], bh0, 0u);
                mma16816(d[gi][nt], Ah[gi][4], bl0, 0u);
            }
        }

        const int nbuf = buf ^ 1;
        if (role == 0) {
            // a = sigm(i) * tanh(g) -> exchange
            #pragma unroll
            for (int nt = 0; nt < 2; ++nt)
                #pragma unroll
                for (int e = 0; e < 4; ++e) {
                    float a = sigm_f(d[0][nt][e]) * tanh_f(d[1][nt][e]);
                    const int u  = ub * 16 + r0 + ((e >= 2) ? 8 : 0);
                    const int cl = nt * 8 + k0 + (e & 1);
                    aEx[np][cl][u] = a;
                }
            // fc1 for s+1 -> nbuf
            if (s + 1 < S_LEN) {
                float v  = tanh_f(fmaf(xv, w1r, b1r));
                float vh = __half2float(__float2half_rn(v));
                if (pr == 0) hHI[np][nbuf][lb][64 + fi] = __float2half_rn(v);
                else         hLO[np][nbuf][lb][64 + fi] = __float2half_rn(v - vh);
            }
            barh(bar1);
            barh(bar2);
        } else {
            float fs[2][4], os[2][4];
            #pragma unroll
            for (int nt = 0; nt < 2; ++nt)
                #pragma unroll
                for (int e = 0; e < 4; ++e) {
                    fs[nt][e] = sigm_f(d[0][nt][e]);
                    os[nt][e] = sigm_f(d[1][nt][e]);
                }
            barh(bar1);
            #pragma unroll
            for (int nt = 0; nt < 2; ++nt)
                #pragma unroll
                for (int e = 0; e < 4; ++e) {
                    const int u  = ub * 16 + r0 + ((e >= 2) ? 8 : 0);
                    const int cl = nt * 8 + k0 + (e & 1);
                    float a  = aEx[np][cl][u];
                    float cc = fs[nt][e] * cst[nt][e] + a;
                    cst[nt][e] = cc;
                    float hh  = os[nt][e] * tanh_f(cc);
                    float hhi = __half2float(__float2half_rn(hh));
                    hHI[np][nbuf][cl][u] = __float2half_rn(hh);
                    hLO[np][nbuf][cl][u] = __float2half_rn(hh - hhi);
                    if (s == S_LEN - 1) hfin[np * 16 + cl][u] = hh;
                }
            barh(bar2);
        }
        buf = nbuf;
    }

    __syncthreads();

    // ---- fc2 ----
    if (tid < 32) {
        float acc = __ldg(b2);
        #pragma unroll
        for (int u = 0; u < 64; ++u)
            acc = fmaf(__ldg(W2 + u), hfin[tid][u], acc);
        out[bbase + tid] = acc;
    }
}

extern "C" void kernel_launch(void* const* d_in, const int* in_sizes, int n_in,
                              void* d_out, int out_size)
{
    const float* x    = (const float*)d_in[0];
    const float* W1   = (const float*)d_in[1];
    const float* b1   = (const float*)d_in[2];
    const float* W_ih = (const float*)d_in[3];
    const float* W_hh = (const float*)d_in[4];
    const float* b_ih = (const float*)d_in[5];
    const float* b_hh = (const float*)d_in[6];
    const float* W2   = (const float*)d_in[7];
    const float* b2   = (const float*)d_in[8];
    float* out = (float*)d_out;

    teprnn2_mma2<<<4096 / BPB, THREADS>>>(
        x, W1, b1, W_ih, W_hh, b_ih, b_hh, W2, b2, out);
}

// round 9
// speedup vs baseline: 1.2596x; 1.2596x over previous
#include <cuda_runtime.h>
#include <cuda_fp16.h>
#include <cstdint>

// TEPRNN2 via warp MMA (HMMA): gates[256,32] = [W_hh|W_ih|bias] x [h|fc1|1].
// fp16 hi/lo split (3 MMAs/tile), fp32 accum, register-local LSTM epilogue.
// R9: fused-rcp epilogue (8 MUFU/elem), anti-phase skew of batch-half groups,
//     fc2 from hi+lo h buffers.

#define S_LEN   256
#define THREADS 256
#define BPB     32
#define HST     88          // halfs per batch column (80 + 8 pad; conflict-free)

__device__ __forceinline__ uint32_t pk(float a, float b){
    __half2 t = __halves2half2(__float2half_rn(a), __float2half_rn(b));
    return *reinterpret_cast<uint32_t*>(&t);
}
__device__ __forceinline__ void mma16816(float* d, const uint32_t* a,
                                         uint32_t b0, uint32_t b1){
    asm volatile(
        "mma.sync.aligned.m16n8k16.row.col.f32.f16.f16.f32 "
        "{%0,%1,%2,%3}, {%4,%5,%6,%7}, {%8,%9}, {%0,%1,%2,%3};"
        : "+f"(d[0]), "+f"(d[1]), "+f"(d[2]), "+f"(d[3])
        : "r"(a[0]), "r"(a[1]), "r"(a[2]), "r"(a[3]), "r"(b0), "r"(b1));
}
__device__ __forceinline__ float tanh_f(float x){   // used only in fc1 (x bounded)
    float e = __expf(fminf(-2.f * x, 80.f));
    return __fdividef(1.f - e, 1.f + e);
}

__global__ __launch_bounds__(THREADS, 1)
void teprnn2_mma(const float* __restrict__ x,
                 const float* __restrict__ W1,
                 const float* __restrict__ b1,
                 const float* __restrict__ W_ih,
                 const float* __restrict__ W_hh,
                 const float* __restrict__ b_ih,
                 const float* __restrict__ b_hh,
                 const float* __restrict__ W2,
                 const float* __restrict__ b2,
                 float* __restrict__ out)
{
    __shared__ __half hHI[2][2][16][HST];   // [np][buf][batch-col][k]
    __shared__ __half hLO[2][2][16][HST];

    const int tid  = threadIdx.x;
    const int w    = tid >> 5;
    const int lane = tid & 31;
    const int ub   = w & 3;        // unit block (16 units)
    const int np   = w >> 2;       // batch half (0: cols 0-15, 1: 16-31)
    const int r0   = lane >> 2;
    const int k0   = (lane & 3) * 2;
    const int bbase = blockIdx.x * BPB;

    // ---- A fragments: Ah/Al[gate][ktile][4] ----
    uint32_t Ah[4][5][4], Al[4][5][4];
    #pragma unroll
    for (int g = 0; g < 4; ++g) {
        const int gr0 = g * 64 + ub * 16 + r0;
        #pragma unroll
        for (int kt = 0; kt < 5; ++kt) {
            const int kb = kt * 16 + k0;
            float v[8];
            if (kt < 4) {
                v[0] = W_hh[gr0 * 64 + kb];        v[1] = W_hh[gr0 * 64 + kb + 1];
                v[2] = W_hh[(gr0+8) * 64 + kb];    v[3] = W_hh[(gr0+8) * 64 + kb + 1];
                v[4] = W_hh[gr0 * 64 + kb + 8];    v[5] = W_hh[gr0 * 64 + kb + 9];
                v[6] = W_hh[(gr0+8) * 64 + kb + 8];v[7] = W_hh[(gr0+8) * 64 + kb + 9];
            } else {
                #pragma unroll
                for (int e = 0; e < 8; ++e) v[e] = 0.f;
                const int ka = 64 + k0, kb2 = ka + 1;
                v[0] = (ka  < 68) ? W_ih[gr0*4 + (ka-64)]      : (ka  == 68 ? b_ih[gr0]   + b_hh[gr0]   : 0.f);
                v[1] = (kb2 < 68) ? W_ih[gr0*4 + (kb2-64)]     : (kb2 == 68 ? b_ih[gr0]   + b_hh[gr0]   : 0.f);
                v[2] = (ka  < 68) ? W_ih[(gr0+8)*4 + (ka-64)]  : (ka  == 68 ? b_ih[gr0+8] + b_hh[gr0+8] : 0.f);
                v[3] = (kb2 < 68) ? W_ih[(gr0+8)*4 + (kb2-64)] : (kb2 == 68 ? b_ih[gr0+8] + b_hh[gr0+8] : 0.f);
            }
            float hi[8], lo[8];
            #pragma unroll
            for (int e = 0; e < 8; ++e) {
                hi[e] = __half2float(__float2half_rn(v[e]));
                lo[e] = v[e] - hi[e];
            }
            Ah[g][kt][0] = pk(hi[0], hi[1]);  Al[g][kt][0] = pk(lo[0], lo[1]);
            Ah[g][kt][1] = pk(hi[2], hi[3]);  Al[g][kt][1] = pk(lo[2], lo[3]);
            Ah[g][kt][2] = pk(hi[4], hi[5]);  Al[g][kt][2] = pk(lo[4], lo[5]);
            Ah[g][kt][3] = pk(hi[6], hi[7]);  Al[g][kt][3] = pk(lo[6], lo[7]);
        }
    }

    // ---- fc1 duty + SMEM init ----
    const int lt = tid & 127;
    const int lb = lt >> 3;
    const int fi = (lt >> 1) & 3;
    const int pr = lt & 1;
    const float w1r = __ldg(W1 + fi);
    const float b1r = __ldg(b1 + fi);
    const float* xrow = x + (size_t)(bbase + np * 16 + lb) * S_LEN;

    {   // zero both B arrays
        __half* p0 = &hHI[0][0][0][0];
        __half* p1 = &hLO[0][0][0][0];
        for (int i = tid; i < 2 * 2 * 16 * HST; i += THREADS) {
            p0[i] = __ushort_as_half(0); p1[i] = __ushort_as_half(0);
        }
    }
    __syncthreads();
    if (tid < 64) {  // const-1 row (k=68), both halves x both bufs
        int idx = tid >> 4;
        hHI[idx >> 1][idx & 1][tid & 15][68] = __float2half_rn(1.f);
    }
    {   // fc1 for step 0 -> buf 0
        float v  = tanh_f(fmaf(__ldg(xrow + 0), w1r, b1r));
        float vh = __half2float(__float2half_rn(v));
        if (pr == 0) hHI[np][0][lb][64 + fi] = __float2half_rn(v);
        else         hLO[np][0][lb][64 + fi] = __float2half_rn(v - vh);
    }
    __syncthreads();   // last block-wide sync before the main loop

    // ---- anti-phase skew: np1 group delayed ~1000 cyc (one-time) ----
    if (np == 1) {
        float dmy = __ldg(b2);     // runtime, bounded
        #pragma unroll 1
        for (int i = 0; i < 250; ++i) dmy = fmaf(dmy, 0.999f, 1.0f);
        if (lane == 0)   // write 0 to an unused pad slot so the chain is live
            hLO[1][0][0][80 + ub] = __float2half_rn(dmy * 0.0f);
    }

    float cst[2][4];
    #pragma unroll
    for (int nt = 0; nt < 2; ++nt)
        #pragma unroll
        for (int e = 0; e < 4; ++e) cst[nt][e] = 0.f;

    int buf = 0;
    for (int s = 0; s < S_LEN; ++s) {
        float xv = (s + 1 < S_LEN) ? __ldg(xrow + s + 1) : 0.f;

        float d[4][2][4];
        #pragma unroll
        for (int g = 0; g < 4; ++g)
            #pragma unroll
            for (int nt = 0; nt < 2; ++nt)
                #pragma unroll
                for (int e = 0; e < 4; ++e) d[g][nt][e] = 0.f;

        const __half* bhp = &hHI[np][buf][0][0];
        const __half* blp = &hLO[np][buf][0][0];

        #pragma unroll
        for (int kt = 0; kt < 4; ++kt) {
            #pragma unroll
            for (int nt = 0; nt < 2; ++nt) {
                const int idx = (nt * 8 + r0) * HST + kt * 16 + k0;
                uint32_t bh0 = *(const uint32_t*)(bhp + idx);
                uint32_t bh1 = *(const uint32_t*)(bhp + idx + 8);
                uint32_t bl0 = *(const uint32_t*)(blp + idx);
                uint32_t bl1 = *(const uint32_t*)(blp + idx + 8);
                #pragma unroll
                for (int g = 0; g < 4; ++g) {
                    mma16816(d[g][nt], Ah[g][kt], bh0, bh1);
                    mma16816(d[g][nt], Al[g][kt], bh0, bh1);
                    mma16816(d[g][nt], Ah[g][kt], bl0, bl1);
                }
            }
        }
        {   // kt = 4 (fc1 + bias rows 64..79) — full 3-term for precision
            #pragma unroll
            for (int nt = 0; nt < 2; ++nt) {
                const int idx = (nt * 8 + r0) * HST + 64 + k0;
                uint32_t bh0 = *(const uint32_t*)(bhp + idx);
                uint32_t bl0 = *(const uint32_t*)(blp + idx);
                #pragma unroll
                for (int g = 0; g < 4; ++g) {
                    mma16816(d[g][nt], Ah[g][4], bh0, 0u);
                    mma16816(d[g][nt], Al[g][4], bh0, 0u);
                    mma16816(d[g][nt], Ah[g][4], bl0, 0u);
                }
            }
        }

        // ---- LSTM epilogue (fused-rcp, register-local) ----
        const int nbuf = buf ^ 1;
        #pragma unroll
        for (int nt = 0; nt < 2; ++nt) {
            #pragma unroll
            for (int e = 0; e < 4; ++e) {
                float pi = d[0][nt][e], pf = d[1][nt][e];
                float pg = d[2][nt][e], po = d[3][nt][e];
                // e_g, e_c are numerators -> clamp to stay finite; denominators
                // may hit inf (divides to correct ±0 limit, never NaN).
                float ei = __expf(-pi);
                float ef = __expf(-pf);
                float eo = __expf(-po);
                float eg = __expf(fminf(-2.f * pg, 80.f));
                float a  = __fdividef(1.f - eg, (1.f + ei) * (1.f + eg));
                float fg = __fdividef(1.f, 1.f + ef);
                float cc = fmaf(fg, cst[nt][e], a);
                cst[nt][e] = cc;
                float ec = __expf(fminf(-2.f * cc, 80.f));
                float hh = __fdividef(1.f - ec, (1.f + eo) * (1.f + ec));
                const int u  = ub * 16 + r0 + ((e >= 2) ? 8 : 0);
                const int cl = nt * 8 + k0 + (e & 1);
                float hhi = __half2float(__float2half_rn(hh));
                hHI[np][nbuf][cl][u] = __float2half_rn(hh);
                hLO[np][nbuf][cl][u] = __float2half_rn(hh - hhi);
            }
        }

        // fc1 for step s+1 -> nbuf
        if (s + 1 < S_LEN) {
            float v  = tanh_f(fmaf(xv, w1r, b1r));
            float vh = __half2float(__float2half_rn(v));
            if (pr == 0) hHI[np][nbuf][lb][64 + fi] = __float2half_rn(v);
            else         hLO[np][nbuf][lb][64 + fi] = __float2half_rn(v - vh);
        }

        asm volatile("bar.sync %0, 128;" :: "r"(np + 1) : "memory");
        buf = nbuf;
    }

    __syncthreads();

    // ---- fc2: h reconstructed from hi+lo (final h is in buffer 0) ----
    if (tid < 32) {
        const int npb = tid >> 4, cl = tid & 15;
        const __half* hi = &hHI[npb][0][cl][0];
        const __half* lo = &hLO[npb][0][cl][0];
        float acc = __ldg(b2);
        #pragma unroll
        for (int u = 0; u < 64; ++u)
            acc = fmaf(__ldg(W2 + u),
                       __half2float(hi[u]) + __half2float(lo[u]), acc);
        out[bbase + tid] = acc;
    }
}

extern "C" void kernel_launch(void* const* d_in, const int* in_sizes, int n_in,
                              void* d_out, int out_size)
{
    const float* x    = (const float*)d_in[0];
    const float* W1   = (const float*)d_in[1];
    const float* b1   = (const float*)d_in[2];
    const float* W_ih = (const float*)d_in[3];
    const float* W_hh = (const float*)d_in[4];
    const float* b_ih = (const float*)d_in[5];
    const float* b_hh = (const float*)d_in[6];
    const float* W2   = (const float*)d_in[7];
    const float* b2   = (const float*)d_in[8];
    float* out = (float*)d_out;

    teprnn2_mma<<<4096 / BPB, THREADS>>>(
        x, W1, b1, W_ih, W_hh, b_ih, b_hh, W2, b2, out);
}

// round 10
// speedup vs baseline: 1.3330x; 1.0583x over previous
#include <cuda_runtime.h>
#include <cuda_fp16.h>
#include <cstdint>

// TEPRNN2 via warp MMA (HMMA): gates[256,32] = W_hh x [h] (K=64) + gx,
// gx = W_ih*fc1 + bias computed exact-fp32 on the FMA pipe as accumulator init.
// fp16 hi/lo split (3 MMAs/tile), fp32 accum, register-local LSTM epilogue.
// R10: kt4 tile removed (20% fewer MMAs), nt-phased MMA/epilogue overlap.

#define S_LEN   256
#define THREADS 256
#define BPB     32
#define HST     72          // halfs per batch column (64 + 8 pad; conflict-free)

__device__ __forceinline__ uint32_t pk(float a, float b){
    __half2 t = __halves2half2(__float2half_rn(a), __float2half_rn(b));
    return *reinterpret_cast<uint32_t*>(&t);
}
__device__ __forceinline__ void mma16816(float* d, const uint32_t* a,
                                         uint32_t b0, uint32_t b1){
    asm volatile(
        "mma.sync.aligned.m16n8k16.row.col.f32.f16.f16.f32 "
        "{%0,%1,%2,%3}, {%4,%5,%6,%7}, {%8,%9}, {%0,%1,%2,%3};"
        : "+f"(d[0]), "+f"(d[1]), "+f"(d[2]), "+f"(d[3])
        : "r"(a[0]), "r"(a[1]), "r"(a[2]), "r"(a[3]), "r"(b0), "r"(b1));
}
__device__ __forceinline__ float tanh_f(float x){   // fc1 only (bounded arg)
    float e = __expf(fminf(-2.f * x, 80.f));
    return __fdividef(1.f - e, 1.f + e);
}

__global__ __launch_bounds__(THREADS, 1)
void teprnn2_mma(const float* __restrict__ x,
                 const float* __restrict__ W1,
                 const float* __restrict__ b1,
                 const float* __restrict__ W_ih,
                 const float* __restrict__ W_hh,
                 const float* __restrict__ b_ih,
                 const float* __restrict__ b_hh,
                 const float* __restrict__ W2,
                 const float* __restrict__ b2,
                 float* __restrict__ out)
{
    __shared__ __half hHI[2][2][16][HST];   // [np][buf][batch-col][k]
    __shared__ __half hLO[2][2][16][HST];
    __shared__ float  fc1f[2][2][16][4];    // [np][buf][batch-col][feat] fp32

    const int tid  = threadIdx.x;
    const int w    = tid >> 5;
    const int lane = tid & 31;
    const int ub   = w & 3;        // unit block (16 units)
    const int np   = w >> 2;       // batch half
    const int r0   = lane >> 2;
    const int k0   = (lane & 3) * 2;
    const int bbase = blockIdx.x * BPB;

    // ---- A fragments (W_hh only): Ah/Al[gate][ktile(4)][4] ----
    uint32_t Ah[4][4][4], Al[4][4][4];
    #pragma unroll
    for (int g = 0; g < 4; ++g) {
        const int gr0 = g * 64 + ub * 16 + r0;
        #pragma unroll
        for (int kt = 0; kt < 4; ++kt) {
            const int kb = kt * 16 + k0;
            float v[8];
            v[0] = W_hh[gr0 * 64 + kb];        v[1] = W_hh[gr0 * 64 + kb + 1];
            v[2] = W_hh[(gr0+8) * 64 + kb];    v[3] = W_hh[(gr0+8) * 64 + kb + 1];
            v[4] = W_hh[gr0 * 64 + kb + 8];    v[5] = W_hh[gr0 * 64 + kb + 9];
            v[6] = W_hh[(gr0+8) * 64 + kb + 8];v[7] = W_hh[(gr0+8) * 64 + kb + 9];
            float hi[8], lo[8];
            #pragma unroll
            for (int e = 0; e < 8; ++e) {
                hi[e] = __half2float(__float2half_rn(v[e]));
                lo[e] = v[e] - hi[e];
            }
            Ah[g][kt][0] = pk(hi[0], hi[1]);  Al[g][kt][0] = pk(lo[0], lo[1]);
            Ah[g][kt][1] = pk(hi[2], hi[3]);  Al[g][kt][1] = pk(lo[2], lo[3]);
            Ah[g][kt][2] = pk(hi[4], hi[5]);  Al[g][kt][2] = pk(lo[4], lo[5]);
            Ah[g][kt][3] = pk(hi[6], hi[7]);  Al[g][kt][3] = pk(lo[6], lo[7]);
        }
    }

    // ---- W_ih + combined bias for this thread's 2 unit rows (exact fp32) ----
    float wih[2][4][4], bse[2][4];
    #pragma unroll
    for (int rr = 0; rr < 2; ++rr)
        #pragma unroll
        for (int g = 0; g < 4; ++g) {
            const int row = g * 64 + ub * 16 + r0 + rr * 8;
            #pragma unroll
            for (int i = 0; i < 4; ++i) wih[rr][g][i] = W_ih[row * 4 + i];
            bse[rr][g] = b_ih[row] + b_hh[row];
        }

    // ---- fc1 duty: 64 threads per np group ----
    const int lt = tid & 127;
    const int lb = lt >> 2;            // batch col 0..15 (lt < 64)
    const int fi = lt & 3;
    const float w1r = __ldg(W1 + (lt < 64 ? fi : 0));
    const float b1r = __ldg(b1 + (lt < 64 ? fi : 0));
    const float* xrow = x + (size_t)(bbase + np * 16 + (lt < 64 ? lb : 0)) * S_LEN;

    {   // zero h arrays (h0 = 0; pads too)
        __half* p0 = &hHI[0][0][0][0];
        __half* p1 = &hLO[0][0][0][0];
        for (int i = tid; i < 2 * 2 * 16 * HST; i += THREADS) {
            p0[i] = __ushort_as_half(0); p1[i] = __ushort_as_half(0);
        }
    }
    if (lt < 64) {  // fc1 for step 0 -> buf 0
        fc1f[np][0][lb][fi] = tanh_f(fmaf(__ldg(xrow + 0), w1r, b1r));
    }
    __syncthreads();   // last block-wide sync before main loop

    // ---- anti-phase skew: np1 delayed ~1000 cyc (one-time) ----
    if (np == 1) {
        float dmy = __ldg(b2);
        #pragma unroll 1
        for (int i = 0; i < 250; ++i) dmy = fmaf(dmy, 0.999f, 1.0f);
        if (lane == 0)
            hLO[1][0][0][64 + ub] = __float2half_rn(dmy * 0.0f);  // pad slot
    }

    float cst[2][4];
    #pragma unroll
    for (int nt = 0; nt < 2; ++nt)
        #pragma unroll
        for (int e = 0; e < 4; ++e) cst[nt][e] = 0.f;

    int buf = 0;
    for (int s = 0; s < S_LEN; ++s) {
        float xv = (s + 1 < S_LEN && lt < 64) ? __ldg(xrow + s + 1) : 0.f;

        // ---- gx = W_ih*fc1 + bias as accumulator init (exact fp32) ----
        float d[2][4][4];   // [nt][g][e]
        {
            float4 f4[2][2];   // [nt][e&1] -> col nt*8 + k0 + e1
            #pragma unroll
            for (int nt = 0; nt < 2; ++nt)
                #pragma unroll
                for (int e1 = 0; e1 < 2; ++e1)
                    f4[nt][e1] = *(const float4*)&fc1f[np][buf][nt * 8 + k0 + e1][0];
            #pragma unroll
            for (int nt = 0; nt < 2; ++nt)
                #pragma unroll
                for (int g = 0; g < 4; ++g)
                    #pragma unroll
                    for (int e = 0; e < 4; ++e) {
                        const int rr = e >> 1, e1 = e & 1;
                        float acc = bse[rr][g];
                        acc = fmaf(wih[rr][g][0], f4[nt][e1].x, acc);
                        acc = fmaf(wih[rr][g][1], f4[nt][e1].y, acc);
                        acc = fmaf(wih[rr][g][2], f4[nt][e1].z, acc);
                        acc = fmaf(wih[rr][g][3], f4[nt][e1].w, acc);
                        d[nt][g][e] = acc;
                    }
        }

        const __half* bhp = &hHI[np][buf][0][0];
        const __half* blp = &hLO[np][buf][0][0];

        // ---- MMA phase, nt=0 then nt=1 (chains finish early for overlap) ----
        #pragma unroll
        for (int nt = 0; nt < 2; ++nt) {
            #pragma unroll
            for (int kt = 0; kt < 4; ++kt) {
                const int idx = (nt * 8 + r0) * HST + kt * 16 + k0;
                uint32_t bh0 = *(const uint32_t*)(bhp + idx);
                uint32_t bh1 = *(const uint32_t*)(bhp + idx + 8);
                uint32_t bl0 = *(const uint32_t*)(blp + idx);
                uint32_t bl1 = *(const uint32_t*)(blp + idx + 8);
                #pragma unroll
                for (int g = 0; g < 4; ++g) {
                    mma16816(d[nt][g], Ah[g][kt], bh0, bh1);
                    mma16816(d[nt][g], Al[g][kt], bh0, bh1);
                    mma16816(d[nt][g], Ah[g][kt], bl0, bl1);
                }
            }
        }

        const int nbuf = buf ^ 1;

        // fc1 for s+1 (MUFU, independent of d) -> overlaps MMA drain
        if (s + 1 < S_LEN && lt < 64)
            fc1f[np][nbuf][lb][fi] = tanh_f(fmaf(xv, w1r, b1r));

        // ---- LSTM epilogue: nt=0 first (overlaps nt=1 MMA drain) ----
        #pragma unroll
        for (int nt = 0; nt < 2; ++nt) {
            #pragma unroll
            for (int e = 0; e < 4; ++e) {
                float pi = d[nt][0][e], pf = d[nt][1][e];
                float pg = d[nt][2][e], po = d[nt][3][e];
                float ei = __expf(-pi);
                float ef = __expf(-pf);
                float eo = __expf(-po);
                float eg = __expf(fminf(-2.f * pg, 80.f));
                float a  = __fdividef(1.f - eg, (1.f + ei) * (1.f + eg));
                float fg = __fdividef(1.f, 1.f + ef);
                float cc = fmaf(fg, cst[nt][e], a);
                cst[nt][e] = cc;
                float ec = __expf(fminf(-2.f * cc, 80.f));
                float hh = __fdividef(1.f - ec, (1.f + eo) * (1.f + ec));
                const int u  = ub * 16 + r0 + ((e >= 2) ? 8 : 0);
                const int cl = nt * 8 + k0 + (e & 1);
                float hhi = __half2float(__float2half_rn(hh));
                hHI[np][nbuf][cl][u] = __float2half_rn(hh);
                hLO[np][nbuf][cl][u] = __float2half_rn(hh - hhi);
            }
        }

        asm volatile("bar.sync %0, 128;" :: "r"(np + 1) : "memory");
        buf = nbuf;
    }

    __syncthreads();

    // ---- fc2: h reconstructed from hi+lo (final h in buffer 0) ----
    if (tid < 32) {
        const int npb = tid >> 4, cl = tid & 15;
        const __half* hi = &hHI[npb][0][cl][0];
        const __half* lo = &hLO[npb][0][cl][0];
        float acc = __ldg(b2);
        #pragma unroll
        for (int u = 0; u < 64; ++u)
            acc = fmaf(__ldg(W2 + u),
                       __half2float(hi[u]) + __half2float(lo[u]), acc);
        out[bbase + tid] = acc;
    }
}

extern "C" void kernel_launch(void* const* d_in, const int* in_sizes, int n_in,
                              void* d_out, int out_size)
{
    const float* x    = (const float*)d_in[0];
    const float* W1   = (const float*)d_in[1];
    const float* b1   = (const float*)d_in[2];
    const float* W_ih = (const float*)d_in[3];
    const float* W_hh = (const float*)d_in[4];
    const float* b_ih = (const float*)d_in[5];
    const float* b_hh = (const float*)d_in[6];
    const float* W2   = (const float*)d_in[7];
    const float* b2   = (const float*)d_in[8];
    float* out = (float*)d_out;

    teprnn2_mma<<<4096 / BPB, THREADS>>>(
        x, W1, b1, W_ih, W_hh, b_ih, b_hh, W2, b2, out);
}

// round 11
// speedup vs baseline: 1.4615x; 1.0963x over previous
#include <cuda_runtime.h>
#include <cuda_fp16.h>
#include <cstdint>

// TEPRNN2 via warp MMA (HMMA): gates = W_hh x h (K=64, fp16 hi/lo 3-MMA) + gx,
// gx = W_ih*fc1 + bias in exact fp32 as accumulator init.
// R11: in-warp 2-stage software pipeline over nt batch-octets — MMA(ntA) tensor
// work drains under epilogue(ntB) MUFU work, every step, deterministically.

#define S_LEN   256
#define THREADS 256
#define BPB     32
#define HST     72          // halfs per batch column (64 + 8 pad; conflict-free)

__device__ __forceinline__ uint32_t pk(float a, float b){
    __half2 t = __halves2half2(__float2half_rn(a), __float2half_rn(b));
    return *reinterpret_cast<uint32_t*>(&t);
}
__device__ __forceinline__ void mma16816(float* d, const uint32_t* a,
                                         uint32_t b0, uint32_t b1){
    asm volatile(
        "mma.sync.aligned.m16n8k16.row.col.f32.f16.f16.f32 "
        "{%0,%1,%2,%3}, {%4,%5,%6,%7}, {%8,%9}, {%0,%1,%2,%3};"
        : "+f"(d[0]), "+f"(d[1]), "+f"(d[2]), "+f"(d[3])
        : "r"(a[0]), "r"(a[1]), "r"(a[2]), "r"(a[3]), "r"(b0), "r"(b1));
}
__device__ __forceinline__ float tanh_f(float x){   // fc1 only (bounded arg)
    float e = __expf(fminf(-2.f * x, 80.f));
    return __fdividef(1.f - e, 1.f + e);
}

__global__ __launch_bounds__(THREADS, 1)
void teprnn2_mma(const float* __restrict__ x,
                 const float* __restrict__ W1,
                 const float* __restrict__ b1,
                 const float* __restrict__ W_ih,
                 const float* __restrict__ W_hh,
                 const float* __restrict__ b_ih,
                 const float* __restrict__ b_hh,
                 const float* __restrict__ W2,
                 const float* __restrict__ b2,
                 float* __restrict__ out)
{
    __shared__ __half hHI[2][2][16][HST];   // [np][buf][batch-col][k]
    __shared__ __half hLO[2][2][16][HST];
    __shared__ float  fc1f[2][2][16][4];    // [np][buf][batch-col][feat] fp32

    const int tid  = threadIdx.x;
    const int w    = tid >> 5;
    const int lane = tid & 31;
    const int ub   = w & 3;        // unit block (16 units)
    const int np   = w >> 2;       // batch half
    const int r0   = lane >> 2;
    const int k0   = (lane & 3) * 2;
    const int bbase = blockIdx.x * BPB;

    // ---- A fragments (W_hh only): Ah/Al[gate][ktile(4)][4] ----
    uint32_t Ah[4][4][4], Al[4][4][4];
    #pragma unroll
    for (int g = 0; g < 4; ++g) {
        const int gr0 = g * 64 + ub * 16 + r0;
        #pragma unroll
        for (int kt = 0; kt < 4; ++kt) {
            const int kb = kt * 16 + k0;
            float v[8];
            v[0] = W_hh[gr0 * 64 + kb];        v[1] = W_hh[gr0 * 64 + kb + 1];
            v[2] = W_hh[(gr0+8) * 64 + kb];    v[3] = W_hh[(gr0+8) * 64 + kb + 1];
            v[4] = W_hh[gr0 * 64 + kb + 8];    v[5] = W_hh[gr0 * 64 + kb + 9];
            v[6] = W_hh[(gr0+8) * 64 + kb + 8];v[7] = W_hh[(gr0+8) * 64 + kb + 9];
            float hi[8], lo[8];
            #pragma unroll
            for (int e = 0; e < 8; ++e) {
                hi[e] = __half2float(__float2half_rn(v[e]));
                lo[e] = v[e] - hi[e];
            }
            Ah[g][kt][0] = pk(hi[0], hi[1]);  Al[g][kt][0] = pk(lo[0], lo[1]);
            Ah[g][kt][1] = pk(hi[2], hi[3]);  Al[g][kt][1] = pk(lo[2], lo[3]);
            Ah[g][kt][2] = pk(hi[4], hi[5]);  Al[g][kt][2] = pk(lo[4], lo[5]);
            Ah[g][kt][3] = pk(hi[6], hi[7]);  Al[g][kt][3] = pk(lo[6], lo[7]);
        }
    }

    // ---- W_ih + combined bias for this thread's 2 unit rows (exact fp32) ----
    float wih[2][4][4], bse[2][4];
    #pragma unroll
    for (int rr = 0; rr < 2; ++rr)
        #pragma unroll
        for (int g = 0; g < 4; ++g) {
            const int row = g * 64 + ub * 16 + r0 + rr * 8;
            #pragma unroll
            for (int i = 0; i < 4; ++i) wih[rr][g][i] = W_ih[row * 4 + i];
            bse[rr][g] = b_ih[row] + b_hh[row];
        }

    // ---- fc1 duty: 64 threads per np group ----
    const int lt = tid & 127;
    const int lb = lt >> 2;
    const int fi = lt & 3;
    const float w1r = __ldg(W1 + (lt < 64 ? fi : 0));
    const float b1r = __ldg(b1 + (lt < 64 ? fi : 0));
    const float* xrow = x + (size_t)(bbase + np * 16 + (lt < 64 ? lb : 0)) * S_LEN;

    {   // zero h arrays (h0 = 0; pads too)
        __half* p0 = &hHI[0][0][0][0];
        __half* p1 = &hLO[0][0][0][0];
        for (int i = tid; i < 2 * 2 * 16 * HST; i += THREADS) {
            p0[i] = __ushort_as_half(0); p1[i] = __ushort_as_half(0);
        }
    }
    if (lt < 64) {
        fc1f[np][0][lb][fi] = tanh_f(fmaf(__ldg(xrow + 0), w1r, b1r));
    }
    __syncthreads();

    // ---- anti-phase skew: np1 delayed (one-time) ----
    if (np == 1) {
        float dmy = __ldg(b2);
        #pragma unroll 1
        for (int i = 0; i < 250; ++i) dmy = fmaf(dmy, 0.999f, 1.0f);
        if (lane == 0)
            hLO[1][0][0][64 + ub] = __float2half_rn(dmy * 0.0f);  // pad slot
    }

    float cst0[4], cst1[4];
    #pragma unroll
    for (int e = 0; e < 4; ++e) { cst0[e] = 0.f; cst1[e] = 0.f; }

    const int barA = np * 2 + 1;
    const int barB = np * 2 + 2;

    // ===== macros over local state =====
    #define GX_INIT(dd, nt, bf)                                               \
        {                                                                     \
            float4 f40 = *(const float4*)&fc1f[np][bf][(nt) * 8 + k0][0];     \
            float4 f41 = *(const float4*)&fc1f[np][bf][(nt) * 8 + k0 + 1][0]; \
            _Pragma("unroll")                                                 \
            for (int g = 0; g < 4; ++g) {                                     \
                _Pragma("unroll")                                             \
                for (int e = 0; e < 4; ++e) {                                 \
                    const int rr = e >> 1;                                    \
                    const float4 f4 = (e & 1) ? f41 : f40;                    \
                    float acc = bse[rr][g];                                   \
                    acc = fmaf(wih[rr][g][0], f4.x, acc);                     \
                    acc = fmaf(wih[rr][g][1], f4.y, acc);                     \
                    acc = fmaf(wih[rr][g][2], f4.z, acc);                     \
                    acc = fmaf(wih[rr][g][3], f4.w, acc);                     \
                    dd[g][e] = acc;                                           \
                }                                                             \
            }                                                                 \
        }

    #define MMA_PHASE(dd, nt, bf)                                             \
        {                                                                     \
            const __half* bhp = &hHI[np][bf][0][0];                           \
            const __half* blp = &hLO[np][bf][0][0];                           \
            _Pragma("unroll")                                                 \
            for (int kt = 0; kt < 4; ++kt) {                                  \
                const int idx = ((nt) * 8 + r0) * HST + kt * 16 + k0;         \
                uint32_t bh0 = *(const uint32_t*)(bhp + idx);                 \
                uint32_t bh1 = *(const uint32_t*)(bhp + idx + 8);             \
                uint32_t bl0 = *(const uint32_t*)(blp + idx);                 \
                uint32_t bl1 = *(const uint32_t*)(blp + idx + 8);             \
                _Pragma("unroll")                                             \
                for (int g = 0; g < 4; ++g) {                                 \
                    mma16816(dd[g], Ah[g][kt], bh0, bh1);                     \
                    mma16816(dd[g], Al[g][kt], bh0, bh1);                     \
                    mma16816(dd[g], Ah[g][kt], bl0, bl1);                     \
                }                                                             \
            }                                                                 \
        }

    #define EPILOGUE(dd, cstv, nt, nbf)                                       \
        {                                                                     \
            _Pragma("unroll")                                                 \
            for (int e = 0; e < 4; ++e) {                                     \
                float pi = dd[0][e], pf = dd[1][e];                           \
                float pg = dd[2][e], po = dd[3][e];                           \
                float ei = __expf(-pi);                                       \
                float ef = __expf(-pf);                                       \
                float eo = __expf(-po);                                       \
                float eg = __expf(fminf(-2.f * pg, 80.f));                    \
                float a  = __fdividef(1.f - eg, (1.f + ei) * (1.f + eg));     \
                float fg = __fdividef(1.f, 1.f + ef);                         \
                float cc = fmaf(fg, cstv[e], a);                              \
                cstv[e] = cc;                                                 \
                float ec = __expf(fminf(-2.f * cc, 80.f));                    \
                float hh = __fdividef(1.f - ec, (1.f + eo) * (1.f + ec));     \
                const int u  = ub * 16 + r0 + ((e >= 2) ? 8 : 0);             \
                const int cl = (nt) * 8 + k0 + (e & 1);                       \
                float hhi = __half2float(__float2half_rn(hh));                \
                hHI[np][nbf][cl][u] = __float2half_rn(hh);                    \
                hLO[np][nbf][cl][u] = __float2half_rn(hh - hhi);              \
            }                                                                 \
        }

    // ---- prologue: launch nt0 pipeline for step 0 ----
    float d0[4][4], d1[4][4];
    GX_INIT(d0, 0, 0);
    MMA_PHASE(d0, 0, 0);

    for (int s = 0; s < S_LEN; ++s) {
        const int buf  = s & 1;
        const int nbuf = buf ^ 1;

        // --- stage: nt1 MMA for step s (tensor) ---
        GX_INIT(d1, 1, buf);
        MMA_PHASE(d1, 1, buf);

        float xv = (s + 1 < S_LEN && lt < 64) ? __ldg(xrow + s + 1) : 0.f;

        // --- epilogue nt0 step s (MUFU, overlaps nt1 MMA drain) ---
        EPILOGUE(d0, cst0, 0, nbuf);
        if (s + 1 < S_LEN && lt < 64)
            fc1f[np][nbuf][lb][fi] = tanh_f(fmaf(xv, w1r, b1r));

        asm volatile("bar.sync %0, 128;" :: "r"(barA) : "memory");

        // --- stage: nt0 MMA for step s+1 (tensor; reads fresh nt0 rows) ---
        GX_INIT(d0, 0, nbuf);
        MMA_PHASE(d0, 0, nbuf);

        // --- epilogue nt1 step s (MUFU, overlaps nt0 MMA drain) ---
        EPILOGUE(d1, cst1, 1, nbuf);

        asm volatile("bar.sync %0, 128;" :: "r"(barB) : "memory");
    }

    #undef GX_INIT
    #undef MMA_PHASE
    #undef EPILOGUE

    __syncthreads();

    // ---- fc2: h reconstructed from hi+lo (final h in buffer 0) ----
    if (tid < 32) {
        const int npb = tid >> 4, cl = tid & 15;
        const __half* hi = &hHI[npb][0][cl][0];
        const __half* lo = &hLO[npb][0][cl][0];
        float acc = __ldg(b2);
        #pragma unroll
        for (int u = 0; u < 64; ++u)
            acc = fmaf(__ldg(W2 + u),
                       __half2float(hi[u]) + __half2float(lo[u]), acc);
        out[bbase + tid] = acc;
    }
}

extern "C" void kernel_launch(void* const* d_in, const int* in_sizes, int n_in,
                              void* d_out, int out_size)
{
    const float* x    = (const float*)d_in[0];
    const float* W1   = (const float*)d_in[1];
    const float* b1   = (const float*)d_in[2];
    const float* W_ih = (const float*)d_in[3];
    const float* W_hh = (const float*)d_in[4];
    const float* b_ih = (const float*)d_in[5];
    const float* b_hh = (const float*)d_in[6];
    const float* W2   = (const float*)d_in[7];
    const float* b2   = (const float*)d_in[8];
    float* out = (float*)d_out;

    teprnn2_mma<<<4096 / BPB, THREADS>>>(
        x, W1, b1, W_ih, W_hh, b_ih, b_hh, W2, b2, out);
}